// round 15
// baseline (speedup 1.0000x reference)
#include <cuda_runtime.h>
#include <math.h>

// ---------------- problem constants ----------------
#define BB   64
#define TT   256
#define EMBD 256
#define PROJ 256
#define RDIM 2048
#define HH   512
#define G4   2048
#define DIN  512
#define KOO  3
#define KRR  2

typedef unsigned long long u64;

// output layout (float32): outputs[B,T,2H], hidden_h[1,B,2H], hidden_c[1,B,2H], embedded[B,T,512]
#define OUT0_N  (64ULL*256ULL*1024ULL)
#define OUT1_O  (OUT0_N)
#define OUT2_O  (OUT1_O + 64ULL*1024ULL)
#define OUT3_O  (OUT2_O + 64ULL*1024ULL)

// recurrence smem: h_s[64][648] + gates[64*32] + c[512] + hn[512] + len[64]
#define HPAD    648
#define SMEM_RECUR ((64*HPAD + 64*32 + 512 + 512 + 64) * 4)

// ---------------- device scratch ----------------
__device__ __align__(16) float g_xw[2][BB*TT][G4];       // precomputed x@Wi^T + bias
__device__ __align__(16) float g_h2[2][2][64][BB][8];    // [dir][phase][cid][b][8] CTA-contiguous h
__device__ unsigned int g_flags[2][64 * 8];              // barrier flags, 32B apart
__device__ int          g_mask_mode;

// ---------------- f32x2 + mem helpers ----------------
__device__ __forceinline__ void FMA2(u64& acc, u64 a, u64 b) {
    asm("fma.rn.f32x2 %0, %1, %2, %0;" : "+l"(acc) : "l"(a), "l"(b));
}
__device__ __forceinline__ u64 ADD2(u64 a, u64 b) {
    u64 r; asm("add.rn.f32x2 %0, %1, %2;" : "=l"(r) : "l"(a), "l"(b)); return r;
}
__device__ __forceinline__ u64 SPLAT2(float x) {
    u64 r; asm("mov.b64 %0, {%1, %2};" : "=l"(r) : "f"(x), "f"(x)); return r;
}
__device__ __forceinline__ float HADD2(u64 v) {
    float lo, hi; asm("mov.b64 {%0, %1}, %2;" : "=f"(lo), "=f"(hi) : "l"(v)); return lo + hi;
}
__device__ __forceinline__ void UNPACK2(u64 v, float& lo, float& hi) {
    asm("mov.b64 {%0, %1}, %2;" : "=f"(lo), "=f"(hi) : "l"(v));
}
__device__ __forceinline__ unsigned LD_ACQ(const unsigned* p) {
    unsigned v;
    asm volatile("ld.acquire.gpu.global.u32 %0, [%1];" : "=r"(v) : "l"(p) : "memory");
    return v;
}
__device__ __forceinline__ void ST_REL(unsigned* p, unsigned v) {
    asm volatile("st.release.gpu.global.u32 [%0], %1;" :: "l"(p), "r"(v) : "memory");
}

__device__ __forceinline__ int get_mask(const void* am, int idx) {
    int mode = g_mask_mode;
    if (mode == 1) return ((const unsigned char*)am)[idx] != 0;
    if (mode == 2) return ((const float*)am)[idx] != 0.0f;
    return ((const int*)am)[idx] != 0;
}

// ---------------- init (+ act_mask dtype sniff in block 0) ----------------
__global__ void k_init(float* out0, const unsigned int* am) {
    if (blockIdx.x == 0) {
        __shared__ int s_mode;
        if (threadIdx.x == 0) s_mode = 0;
        __syncthreads();
        int mode = 0;
        for (int i = threadIdx.x; i < 4096; i += blockDim.x) {
            unsigned v = am[i];
            if (v == 0x3f800000u)        mode = 2;
            else if (v > 1u && mode < 2) mode = 1;
        }
        if (mode) atomicMax(&s_mode, mode);
        __syncthreads();
        if (threadIdx.x == 0) g_mask_mode = s_mode;
    }
    size_t stride = (size_t)gridDim.x * blockDim.x;
    size_t tid = (size_t)blockIdx.x * blockDim.x + threadIdx.x;
    float4 z = make_float4(0.f, 0.f, 0.f, 0.f);
    float4* o4 = (float4*)out0;
    for (size_t i = tid; i < OUT0_N / 4; i += stride) o4[i] = z;
    float* gh = &g_h2[0][0][0][0][0];
    for (size_t i = tid; i < 2ULL * 2ULL * 64ULL * BB * 8ULL; i += stride) gh[i] = 0.f;
    unsigned* fl = &g_flags[0][0];
    for (size_t i = tid; i < 2ULL * 64 * 8; i += stride) fl[i] = 0u;
}

// ---------------- res GEMM + fused embedding ----------------
__global__ __launch_bounds__(256) void k_res(const float* feats, const float* W,
                                             const float* b_res, const void* am,
                                             const int* act_ids, const int* obs_ids,
                                             const float* act_emb, const float* obs_emb,
                                             float* emb_out) {
    __shared__ float As[8][64];
    __shared__ float Bs[8][128];
    __shared__ float bias_s[128];
    int m0 = (blockIdx.x >> 1) * 64;
    int n0 = (blockIdx.x & 1) * 128;
    int tid = threadIdx.x;
    if (tid < 128) bias_s[tid] = 2.f * b_res[n0 + tid];

    if (n0 == 0) {
        for (int i = tid; i < 64 * 64; i += 256) {
            int bt = m0 + (i >> 6);
            int c4 = (i & 63) * 4;
            float4 v;
            if (get_mask(am, bt)) {
                int id = act_ids[bt];
                v = *(const float4*)(act_emb + (size_t)id * EMBD + c4);
            } else {
                v = make_float4(0.f, 0.f, 0.f, 0.f);
#pragma unroll
                for (int k = 0; k < KOO; ++k) {
                    int id = obs_ids[bt * KOO + k];
                    if (id != 0) {
                        float4 e = *(const float4*)(obs_emb + (size_t)id * EMBD + c4);
                        v.x += e.x; v.y += e.y; v.z += e.z; v.w += e.w;
                    }
                }
            }
            *(float4*)(emb_out + (size_t)bt * 512 + c4) = v;
        }
    }

    int tx = tid & 31, ty = tid >> 5;
    int arow = (tid & 127) >> 1, acol = (tid & 1) * 4;
    int brow = tid >> 1, bcol = (tid & 1) * 4;

    const float* Abase = feats + (size_t)(m0 + arow) * (KRR * RDIM);
    const float* Bbase = W + (size_t)(n0 + brow) * RDIM;

    u64 acc2[4][4];
#pragma unroll
    for (int i = 0; i < 4; ++i)
#pragma unroll
        for (int j = 0; j < 4; ++j) acc2[i][j] = 0ULL;

    float4 a0, a1, bv;
    if (tid < 128) {
        a0 = *(const float4*)(Abase + acol);
        a1 = *(const float4*)(Abase + RDIM + acol);
    }
    bv = *(const float4*)(Bbase + bcol);

    for (int k0 = 0; k0 < RDIM; k0 += 8) {
        __syncthreads();
        if (tid < 128) {
            As[acol + 0][arow] = a0.x + a1.x;
            As[acol + 1][arow] = a0.y + a1.y;
            As[acol + 2][arow] = a0.z + a1.z;
            As[acol + 3][arow] = a0.w + a1.w;
        }
        Bs[bcol + 0][brow] = bv.x;
        Bs[bcol + 1][brow] = bv.y;
        Bs[bcol + 2][brow] = bv.z;
        Bs[bcol + 3][brow] = bv.w;
        __syncthreads();
        if (k0 + 8 < RDIM) {
            if (tid < 128) {
                a0 = *(const float4*)(Abase + k0 + 8 + acol);
                a1 = *(const float4*)(Abase + RDIM + k0 + 8 + acol);
            }
            bv = *(const float4*)(Bbase + k0 + 8 + bcol);
        }
#pragma unroll
        for (int kk = 0; kk < 8; ++kk) {
            const ulonglong2* pA = (const ulonglong2*)&As[kk][ty * 8];
            ulonglong2 qa0 = pA[0], qa1 = pA[1];
            u64 ra[4] = {qa0.x, qa0.y, qa1.x, qa1.y};
            float4 nv = *(float4*)&Bs[kk][tx * 4];
            u64 rb[4] = {SPLAT2(nv.x), SPLAT2(nv.y), SPLAT2(nv.z), SPLAT2(nv.w)};
#pragma unroll
            for (int i = 0; i < 4; ++i)
#pragma unroll
                for (int j = 0; j < 4; ++j) FMA2(acc2[i][j], ra[i], rb[j]);
        }
    }
#pragma unroll
    for (int i2 = 0; i2 < 4; ++i2) {
        int me = m0 + ty * 8 + i2 * 2;
        int msk_e = get_mask(am, me);
        int msk_o = get_mask(am, me + 1);
        float* oe = emb_out + (size_t)me * 512 + 256 + n0;
        float* oo = oe + 512;
#pragma unroll
        for (int j = 0; j < 4; ++j) {
            int n = tx * 4 + j;
            float lo, hi; UNPACK2(acc2[i2][j], lo, hi);
            oe[n] = msk_e ? 0.f : (lo + bias_s[n]);
            oo[n] = msk_o ? 0.f : (hi + bias_s[n]);
        }
    }
}

// ---------------- xw GEMM: BM=128 = 2 batches x 64 steps, BN=128, BK=16, padded Bs ----------------
__global__ __launch_bounds__(256) void k_xw(const float* emb,
                                            const float* Wi_f, const float* bi_f, const float* bh_f,
                                            const float* Wi_b, const float* bi_b, const float* bh_b,
                                            const int* lengths) {
    int dir = blockIdx.z;
    const float* Wi = dir ? Wi_b : Wi_f;
    const float* bi = dir ? bi_b : bi_f;
    const float* bh = dir ? bh_b : bh_f;
    int by = blockIdx.y;
    int b0 = (by >> 2) * 2;
    int s0 = (by & 3) * 64;
    int n0 = blockIdx.x * 128;
    int len0 = lengths[b0];
    if (s0 >= len0) return;
    int len1 = lengths[b0 + 1];

    __shared__ float As[16][128];
    __shared__ float Bs[16][192];
    __shared__ float bias_s[128];
    int tid = threadIdx.x;
    if (tid < 128) bias_s[tid] = bi[n0 + tid] + bh[n0 + tid];
    int arow = tid >> 1, acol = (tid & 1) * 8;
    int boff = (arow >> 3) * 12 + (arow & 7);
    int tx = tid & 15, ty = tid >> 4;

    int ab = b0 + (arow >> 6);
    int as = s0 + (arow & 63);
    int alen = (arow >> 6) ? len1 : len0;
    int t = dir ? (alen - 1 - as) : as;
    if (t < 0) t = 0;
    if (t > 255) t = 255;
    const float* Arow = emb + ((size_t)(ab * TT + t)) * 512;
    const float* Brow = Wi + (size_t)(n0 + arow) * 512;

    u64 acc2[4][8];
#pragma unroll
    for (int i = 0; i < 4; ++i)
#pragma unroll
        for (int j = 0; j < 8; ++j) acc2[i][j] = 0ULL;

    float4 av0 = *(const float4*)(Arow + acol);
    float4 av1 = *(const float4*)(Arow + acol + 4);
    float4 bv0 = *(const float4*)(Brow + acol);
    float4 bv1 = *(const float4*)(Brow + acol + 4);

    for (int k0 = 0; k0 < 512; k0 += 16) {
        __syncthreads();
        As[acol + 0][arow] = av0.x; As[acol + 1][arow] = av0.y;
        As[acol + 2][arow] = av0.z; As[acol + 3][arow] = av0.w;
        As[acol + 4][arow] = av1.x; As[acol + 5][arow] = av1.y;
        As[acol + 6][arow] = av1.z; As[acol + 7][arow] = av1.w;
        Bs[acol + 0][boff] = bv0.x; Bs[acol + 1][boff] = bv0.y;
        Bs[acol + 2][boff] = bv0.z; Bs[acol + 3][boff] = bv0.w;
        Bs[acol + 4][boff] = bv1.x; Bs[acol + 5][boff] = bv1.y;
        Bs[acol + 6][boff] = bv1.z; Bs[acol + 7][boff] = bv1.w;
        __syncthreads();
        if (k0 + 16 < 512) {
            av0 = *(const float4*)(Arow + k0 + 16 + acol);
            av1 = *(const float4*)(Arow + k0 + 16 + acol + 4);
            bv0 = *(const float4*)(Brow + k0 + 16 + acol);
            bv1 = *(const float4*)(Brow + k0 + 16 + acol + 4);
        }
#pragma unroll
        for (int kk = 0; kk < 16; ++kk) {
            const ulonglong2* pA = (const ulonglong2*)&As[kk][ty * 8];
            ulonglong2 qa0 = pA[0], qa1 = pA[1];
            u64 ra[4] = {qa0.x, qa0.y, qa1.x, qa1.y};
            float4 b0v = *(float4*)&Bs[kk][tx * 12];
            float4 b1v = *(float4*)&Bs[kk][tx * 12 + 4];
            u64 rb[8] = {SPLAT2(b0v.x), SPLAT2(b0v.y), SPLAT2(b0v.z), SPLAT2(b0v.w),
                         SPLAT2(b1v.x), SPLAT2(b1v.y), SPLAT2(b1v.z), SPLAT2(b1v.w)};
#pragma unroll
            for (int i = 0; i < 4; ++i)
#pragma unroll
                for (int j = 0; j < 8; ++j) FMA2(acc2[i][j], ra[i], rb[j]);
        }
    }
#pragma unroll
    for (int i2 = 0; i2 < 4; ++i2) {
        int rr = ty * 8 + i2 * 2;
        int ob = b0 + (rr >> 6);
        int os = s0 + (rr & 63);
        float* oe = &g_xw[dir][ob * TT + os][0];
        float* oo = oe + G4;
#pragma unroll
        for (int j = 0; j < 8; ++j) {
            int n = tx * 8 + j;
            float lo, hi; UNPACK2(acc2[i2][j], lo, hi);
            float bb = bias_s[n];
            oe[n0 + n] = lo + bb;
            oo[n0 + n] = hi + bb;
        }
    }
}

// ---------------- persistent recurrence v11: merged phases + reg-fed d_out + unroll 4 ----------------
__global__ __launch_bounds__(256, 1) void k_recur(const float* Wh_f, const float* Wh_b,
                                                  const int* lengths, float* d_out) {
    extern __shared__ float sm_f[];
    float* h_s     = sm_f;                       // 64 * 648 padded h
    float* gates_s = sm_f + 64 * HPAD;           // 64 * 32
    float* c_s     = gates_s + 64 * 32;          // 512
    float* hn_s    = c_s + 512;                  // 512 persistent current h
    int*   len_s   = (int*)(hn_s + 512);         // 64

    int dir = blockIdx.x >> 6;
    int cid = blockIdx.x & 63;
    int j0 = cid * 8;
    const float* Wh = dir ? Wh_b : Wh_f;
    int tid = threadIdx.x;
    int w = tid >> 5, lane = tid & 31;

    if (tid < 64) len_s[tid] = lengths[tid];
    for (int i = tid; i < 512; i += 256) { c_s[i] = 0.f; hn_s[i] = 0.f; }

    u64 wq[4][8];
#pragma unroll
    for (int r = 0; r < 4; ++r) {
        int lr = w * 4 + r;
        int grow = (lr >> 3) * 512 + j0 + (lr & 7);
        const ulonglong2* wsrc = (const ulonglong2*)(Wh + (size_t)grow * 512 + lane * 16);
#pragma unroll
        for (int q = 0; q < 4; ++q) {
            ulonglong2 v = wsrc[q];
            wq[r][2 * q] = v.x; wq[r][2 * q + 1] = v.y;
        }
    }
    __syncthreads();

    unsigned* flags = &g_flags[dir][0];
    int nact = 64;

    float xg[2][4];
#pragma unroll
    for (int rep = 0; rep < 2; ++rep) {
        int it = tid + rep * 256;
        int bb2 = it >> 3, jj = it & 7;
        const float* xwrow = &g_xw[dir][bb2 * TT + 0][0];
        int col = j0 + jj;
        xg[rep][0] = xwrow[col];
        xg[rep][1] = xwrow[512 + col];
        xg[rep][2] = xwrow[1024 + col];
        xg[rep][3] = xwrow[1536 + col];
    }

    for (int t = 0; t < TT; ++t) {
        if (nact == 0) break;

        // ---- stage h_prev: coalesced LDG, conflict-free scattered STS ----
        {
            int nact2 = 8;
            while (nact2 < nact) nact2 <<= 1;
            int lg = __ffs(nact2) - 1;
            const float4* hr4 = (const float4*)&g_h2[dir][t & 1][0][0][0];
            float4* hs4 = (float4*)h_s;
            int total = (64 << lg) << 1;
            for (int i = tid; i < total; i += 256) {
                int half = i & 1;
                int b = (i >> 1) & (nact2 - 1);
                int c2 = i >> (1 + lg);
                float4 v = hr4[c2 * 128 + b * 2 + half];
                hs4[b * (HPAD / 4) + (c2 >> 1) * 5 + (c2 & 1) * 2 + half] = v;
            }
        }
        __syncthreads();

        // ---- Wh @ h from smem (unroll 4 for cross-b ILP over the shuffle chains) ----
#pragma unroll 4
        for (int b = 0; b < nact; ++b) {
            const ulonglong2* hp = (const ulonglong2*)(h_s + b * HPAD + lane * 20);
            ulonglong2 v0 = hp[0], v1 = hp[1], v2 = hp[2], v3 = hp[3];
            u64 hv[8] = {v0.x, v0.y, v1.x, v1.y, v2.x, v2.y, v3.x, v3.y};
            u64 a0 = 0ULL, a1 = 0ULL, a2 = 0ULL, a3 = 0ULL;
#pragma unroll
            for (int q = 0; q < 8; ++q) {
                FMA2(a0, wq[0][q], hv[q]);
                FMA2(a1, wq[1][q], hv[q]);
                FMA2(a2, wq[2][q], hv[q]);
                FMA2(a3, wq[3][q], hv[q]);
            }
            float s0 = HADD2(a0), s1 = HADD2(a1), s2 = HADD2(a2), s3 = HADD2(a3);
            float u  = (lane & 1) ? s1 : s0;
            float us = (lane & 1) ? s0 : s1;
            u += __shfl_xor_sync(0xffffffffu, us, 1);
            float x  = (lane & 1) ? s3 : s2;
            float xs = (lane & 1) ? s2 : s3;
            x += __shfl_xor_sync(0xffffffffu, xs, 1);
            float p  = (lane & 2) ? x : u;
            float ps = (lane & 2) ? u : x;
            p += __shfl_xor_sync(0xffffffffu, ps, 2);
            p += __shfl_xor_sync(0xffffffffu, p, 4);
            p += __shfl_xor_sync(0xffffffffu, p, 8);
            p += __shfl_xor_sync(0xffffffffu, p, 16);
            if (lane < 4) gates_s[b * 32 + w * 4 + lane] = p;
        }
        __syncthreads();

        // ---- gate math + direct coalesced h publish (g_h2) + hn in registers ----
        float hnv[2];
        float* hw = &g_h2[dir][(t + 1) & 1][cid][0][0];
#pragma unroll
        for (int rep = 0; rep < 2; ++rep) {
            int it = tid + rep * 256;
            int b = it >> 3, jj = it & 7;
            if (b < nact) {
                float gi = gates_s[b * 32 + jj]      + xg[rep][0];
                float gf = gates_s[b * 32 + 8 + jj]  + xg[rep][1];
                float gg = gates_s[b * 32 + 16 + jj] + xg[rep][2];
                float go = gates_s[b * 32 + 24 + jj] + xg[rep][3];
                gi = 1.f / (1.f + __expf(-gi));
                gf = 1.f / (1.f + __expf(-gf));
                gg = tanhf(gg);
                go = 1.f / (1.f + __expf(-go));
                float c = gf * c_s[b * 8 + jj] + gi * gg;
                c_s[b * 8 + jj] = c;
                float hn = go * tanhf(c);
                hn_s[b * 8 + jj] = hn;
                hw[it] = hn;                 // coalesced STG.32 publish
                hnv[rep] = hn;
            }
        }
        __syncthreads();
        if (tid == 0) ST_REL(&flags[cid * 8], (unsigned)(t + 1));

        // ---- hidden in barrier wait: d_out stores (from regs) + next xg prefetch ----
#pragma unroll
        for (int rep = 0; rep < 2; ++rep) {
            int it = tid + rep * 256;
            int b = it >> 3, jj = it & 7;
            if (b < nact) {
                int tout = dir ? (len_s[b] - 1 - t) : t;
                d_out[((size_t)(b * TT + tout)) * 1024 + (size_t)dir * 512 + j0 + jj] =
                    hnv[rep];
            }
        }
        int nn = nact;
        while (nn > 0 && len_s[nn - 1] <= t + 1) --nn;
#pragma unroll
        for (int rep = 0; rep < 2; ++rep) {
            int it = tid + rep * 256;
            int bb2 = it >> 3, jj = it & 7;
            if (bb2 < nn) {
                const float* xwrow = &g_xw[dir][bb2 * TT + (t + 1)][0];
                int col = j0 + jj;
                xg[rep][0] = xwrow[col];
                xg[rep][1] = xwrow[512 + col];
                xg[rep][2] = xwrow[1024 + col];
                xg[rep][3] = xwrow[1536 + col];
            }
        }

        if (tid < 64) {
            while (LD_ACQ(&flags[tid * 8]) < (unsigned)(t + 1)) { }
        }
        __syncthreads();
        nact = nn;
    }

    for (int i = tid; i < 512; i += 256) {
        int b = i >> 3, jj = i & 7;
        int col = j0 + jj;
        d_out[OUT1_O + (size_t)b * 1024 + (size_t)dir * 512 + col] = hn_s[b * 8 + jj];
        d_out[OUT2_O + (size_t)b * 1024 + (size_t)dir * 512 + col] = c_s[b * 8 + jj];
    }
}

// ---------------- launch ----------------
extern "C" void kernel_launch(void* const* d_in, const int* in_sizes, int n_in,
                              void* d_out, int out_size) {
    const void*  act_mask  = d_in[0];
    const int*   act_ids   = (const int*)d_in[1];
    const int*   obs_ids   = (const int*)d_in[2];
    const float* res_feats = (const float*)d_in[3];
    const int*   lengths   = (const int*)d_in[4];
    const float* act_emb   = (const float*)d_in[5];
    const float* obs_emb   = (const float*)d_in[6];
    const float* W_res     = (const float*)d_in[7];
    const float* b_res     = (const float*)d_in[8];
    const float* Wi_f      = (const float*)d_in[9];
    const float* Wh_f      = (const float*)d_in[10];
    const float* bi_f      = (const float*)d_in[11];
    const float* bh_f      = (const float*)d_in[12];
    const float* Wi_b      = (const float*)d_in[13];
    const float* Wh_b      = (const float*)d_in[14];
    const float* bi_b      = (const float*)d_in[15];
    const float* bh_b      = (const float*)d_in[16];

    float* out = (float*)d_out;
    float* emb_out = out + OUT3_O;

    cudaFuncSetAttribute(k_recur, cudaFuncAttributeMaxDynamicSharedMemorySize, SMEM_RECUR);

    k_init<<<2048, 256>>>(out, (const unsigned int*)act_mask);
    k_res<<<512, 256>>>(res_feats, W_res, b_res, act_mask,
                        act_ids, obs_ids, act_emb, obs_emb, emb_out);
    {
        dim3 g(G4 / 128, (BB * TT) / 128, 2);
        k_xw<<<g, 256>>>(emb_out, Wi_f, bi_f, bh_f, Wi_b, bi_b, bh_b, lengths);
    }
    k_recur<<<128, 256, SMEM_RECUR>>>(Wh_f, Wh_b, lengths, out);
}

// round 16
// speedup vs baseline: 1.0256x; 1.0256x over previous
#include <cuda_runtime.h>
#include <math.h>

// ---------------- problem constants ----------------
#define BB   64
#define TT   256
#define EMBD 256
#define PROJ 256
#define RDIM 2048
#define HH   512
#define G4   2048
#define DIN  512
#define KOO  3
#define KRR  2

typedef unsigned long long u64;

// output layout (float32): outputs[B,T,2H], hidden_h[1,B,2H], hidden_c[1,B,2H], embedded[B,T,512]
#define OUT0_N  (64ULL*256ULL*1024ULL)
#define OUT1_O  (OUT0_N)
#define OUT2_O  (OUT1_O + 64ULL*1024ULL)
#define OUT3_O  (OUT2_O + 64ULL*1024ULL)

// recurrence smem: h_s[64][648] + gates[64*32] + c[512] + hn[512] + len[64]
#define HPAD    648
#define SMEM_RECUR ((64*HPAD + 64*32 + 512 + 512 + 64) * 4)

// ---------------- device scratch ----------------
__device__ __align__(16) float g_xw[2][BB*TT][G4];       // precomputed x@Wi^T + bias
__device__ __align__(16) float g_h2[2][2][64][BB][8];    // [dir][phase][cid][b][8] CTA-contiguous h
__device__ unsigned int g_flags[2][64 * 8];              // barrier flags, 32B apart
__device__ int          g_mask_mode;

// ---------------- f32x2 + mem helpers ----------------
__device__ __forceinline__ void FMA2(u64& acc, u64 a, u64 b) {
    asm("fma.rn.f32x2 %0, %1, %2, %0;" : "+l"(acc) : "l"(a), "l"(b));
}
__device__ __forceinline__ u64 ADD2(u64 a, u64 b) {
    u64 r; asm("add.rn.f32x2 %0, %1, %2;" : "=l"(r) : "l"(a), "l"(b)); return r;
}
__device__ __forceinline__ u64 SPLAT2(float x) {
    u64 r; asm("mov.b64 %0, {%1, %2};" : "=l"(r) : "f"(x), "f"(x)); return r;
}
__device__ __forceinline__ float HADD2(u64 v) {
    float lo, hi; asm("mov.b64 {%0, %1}, %2;" : "=f"(lo), "=f"(hi) : "l"(v)); return lo + hi;
}
__device__ __forceinline__ void UNPACK2(u64 v, float& lo, float& hi) {
    asm("mov.b64 {%0, %1}, %2;" : "=f"(lo), "=f"(hi) : "l"(v));
}
__device__ __forceinline__ unsigned LD_ACQ(const unsigned* p) {
    unsigned v;
    asm volatile("ld.acquire.gpu.global.u32 %0, [%1];" : "=r"(v) : "l"(p) : "memory");
    return v;
}
__device__ __forceinline__ void ST_REL(unsigned* p, unsigned v) {
    asm volatile("st.release.gpu.global.u32 [%0], %1;" :: "l"(p), "r"(v) : "memory");
}

__device__ __forceinline__ int get_mask(const void* am, int idx) {
    int mode = g_mask_mode;
    if (mode == 1) return ((const unsigned char*)am)[idx] != 0;
    if (mode == 2) return ((const float*)am)[idx] != 0.0f;
    return ((const int*)am)[idx] != 0;
}

// ---------------- init (+ act_mask dtype sniff in block 0) ----------------
__global__ void k_init(float* out0, const unsigned int* am) {
    if (blockIdx.x == 0) {
        __shared__ int s_mode;
        if (threadIdx.x == 0) s_mode = 0;
        __syncthreads();
        int mode = 0;
        for (int i = threadIdx.x; i < 4096; i += blockDim.x) {
            unsigned v = am[i];
            if (v == 0x3f800000u)        mode = 2;
            else if (v > 1u && mode < 2) mode = 1;
        }
        if (mode) atomicMax(&s_mode, mode);
        __syncthreads();
        if (threadIdx.x == 0) g_mask_mode = s_mode;
    }
    size_t stride = (size_t)gridDim.x * blockDim.x;
    size_t tid = (size_t)blockIdx.x * blockDim.x + threadIdx.x;
    float4 z = make_float4(0.f, 0.f, 0.f, 0.f);
    float4* o4 = (float4*)out0;
    for (size_t i = tid; i < OUT0_N / 4; i += stride) o4[i] = z;
    float* gh = &g_h2[0][0][0][0][0];
    for (size_t i = tid; i < 2ULL * 2ULL * 64ULL * BB * 8ULL; i += stride) gh[i] = 0.f;
    unsigned* fl = &g_flags[0][0];
    for (size_t i = tid; i < 2ULL * 64 * 8; i += stride) fl[i] = 0u;
}

// ---------------- res GEMM + fused embedding ----------------
__global__ __launch_bounds__(256) void k_res(const float* feats, const float* W,
                                             const float* b_res, const void* am,
                                             const int* act_ids, const int* obs_ids,
                                             const float* act_emb, const float* obs_emb,
                                             float* emb_out) {
    __shared__ float As[8][64];
    __shared__ float Bs[8][128];
    __shared__ float bias_s[128];
    int m0 = (blockIdx.x >> 1) * 64;
    int n0 = (blockIdx.x & 1) * 128;
    int tid = threadIdx.x;
    if (tid < 128) bias_s[tid] = 2.f * b_res[n0 + tid];

    if (n0 == 0) {
        for (int i = tid; i < 64 * 64; i += 256) {
            int bt = m0 + (i >> 6);
            int c4 = (i & 63) * 4;
            float4 v;
            if (get_mask(am, bt)) {
                int id = act_ids[bt];
                v = *(const float4*)(act_emb + (size_t)id * EMBD + c4);
            } else {
                v = make_float4(0.f, 0.f, 0.f, 0.f);
#pragma unroll
                for (int k = 0; k < KOO; ++k) {
                    int id = obs_ids[bt * KOO + k];
                    if (id != 0) {
                        float4 e = *(const float4*)(obs_emb + (size_t)id * EMBD + c4);
                        v.x += e.x; v.y += e.y; v.z += e.z; v.w += e.w;
                    }
                }
            }
            *(float4*)(emb_out + (size_t)bt * 512 + c4) = v;
        }
    }

    int tx = tid & 31, ty = tid >> 5;
    int arow = (tid & 127) >> 1, acol = (tid & 1) * 4;
    int brow = tid >> 1, bcol = (tid & 1) * 4;

    const float* Abase = feats + (size_t)(m0 + arow) * (KRR * RDIM);
    const float* Bbase = W + (size_t)(n0 + brow) * RDIM;

    u64 acc2[4][4];
#pragma unroll
    for (int i = 0; i < 4; ++i)
#pragma unroll
        for (int j = 0; j < 4; ++j) acc2[i][j] = 0ULL;

    float4 a0, a1, bv;
    if (tid < 128) {
        a0 = *(const float4*)(Abase + acol);
        a1 = *(const float4*)(Abase + RDIM + acol);
    }
    bv = *(const float4*)(Bbase + bcol);

    for (int k0 = 0; k0 < RDIM; k0 += 8) {
        __syncthreads();
        if (tid < 128) {
            As[acol + 0][arow] = a0.x + a1.x;
            As[acol + 1][arow] = a0.y + a1.y;
            As[acol + 2][arow] = a0.z + a1.z;
            As[acol + 3][arow] = a0.w + a1.w;
        }
        Bs[bcol + 0][brow] = bv.x;
        Bs[bcol + 1][brow] = bv.y;
        Bs[bcol + 2][brow] = bv.z;
        Bs[bcol + 3][brow] = bv.w;
        __syncthreads();
        if (k0 + 8 < RDIM) {
            if (tid < 128) {
                a0 = *(const float4*)(Abase + k0 + 8 + acol);
                a1 = *(const float4*)(Abase + RDIM + k0 + 8 + acol);
            }
            bv = *(const float4*)(Bbase + k0 + 8 + bcol);
        }
#pragma unroll
        for (int kk = 0; kk < 8; ++kk) {
            const ulonglong2* pA = (const ulonglong2*)&As[kk][ty * 8];
            ulonglong2 qa0 = pA[0], qa1 = pA[1];
            u64 ra[4] = {qa0.x, qa0.y, qa1.x, qa1.y};
            float4 nv = *(float4*)&Bs[kk][tx * 4];
            u64 rb[4] = {SPLAT2(nv.x), SPLAT2(nv.y), SPLAT2(nv.z), SPLAT2(nv.w)};
#pragma unroll
            for (int i = 0; i < 4; ++i)
#pragma unroll
                for (int j = 0; j < 4; ++j) FMA2(acc2[i][j], ra[i], rb[j]);
        }
    }
#pragma unroll
    for (int i2 = 0; i2 < 4; ++i2) {
        int me = m0 + ty * 8 + i2 * 2;
        int msk_e = get_mask(am, me);
        int msk_o = get_mask(am, me + 1);
        float* oe = emb_out + (size_t)me * 512 + 256 + n0;
        float* oo = oe + 512;
#pragma unroll
        for (int j = 0; j < 4; ++j) {
            int n = tx * 4 + j;
            float lo, hi; UNPACK2(acc2[i2][j], lo, hi);
            oe[n] = msk_e ? 0.f : (lo + bias_s[n]);
            oo[n] = msk_o ? 0.f : (hi + bias_s[n]);
        }
    }
}

// ---------------- xw GEMM: BM=128 = 2 batches x 64 steps, BN=128, BK=16, padded Bs ----------------
__global__ __launch_bounds__(256) void k_xw(const float* emb,
                                            const float* Wi_f, const float* bi_f, const float* bh_f,
                                            const float* Wi_b, const float* bi_b, const float* bh_b,
                                            const int* lengths) {
    int dir = blockIdx.z;
    const float* Wi = dir ? Wi_b : Wi_f;
    const float* bi = dir ? bi_b : bi_f;
    const float* bh = dir ? bh_b : bh_f;
    int by = blockIdx.y;
    int b0 = (by >> 2) * 2;
    int s0 = (by & 3) * 64;
    int n0 = blockIdx.x * 128;
    int len0 = lengths[b0];
    if (s0 >= len0) return;
    int len1 = lengths[b0 + 1];

    __shared__ float As[16][128];
    __shared__ float Bs[16][192];
    __shared__ float bias_s[128];
    int tid = threadIdx.x;
    if (tid < 128) bias_s[tid] = bi[n0 + tid] + bh[n0 + tid];
    int arow = tid >> 1, acol = (tid & 1) * 8;
    int boff = (arow >> 3) * 12 + (arow & 7);
    int tx = tid & 15, ty = tid >> 4;

    int ab = b0 + (arow >> 6);
    int as = s0 + (arow & 63);
    int alen = (arow >> 6) ? len1 : len0;
    int t = dir ? (alen - 1 - as) : as;
    if (t < 0) t = 0;
    if (t > 255) t = 255;
    const float* Arow = emb + ((size_t)(ab * TT + t)) * 512;
    const float* Brow = Wi + (size_t)(n0 + arow) * 512;

    u64 acc2[4][8];
#pragma unroll
    for (int i = 0; i < 4; ++i)
#pragma unroll
        for (int j = 0; j < 8; ++j) acc2[i][j] = 0ULL;

    float4 av0 = *(const float4*)(Arow + acol);
    float4 av1 = *(const float4*)(Arow + acol + 4);
    float4 bv0 = *(const float4*)(Brow + acol);
    float4 bv1 = *(const float4*)(Brow + acol + 4);

    for (int k0 = 0; k0 < 512; k0 += 16) {
        __syncthreads();
        As[acol + 0][arow] = av0.x; As[acol + 1][arow] = av0.y;
        As[acol + 2][arow] = av0.z; As[acol + 3][arow] = av0.w;
        As[acol + 4][arow] = av1.x; As[acol + 5][arow] = av1.y;
        As[acol + 6][arow] = av1.z; As[acol + 7][arow] = av1.w;
        Bs[acol + 0][boff] = bv0.x; Bs[acol + 1][boff] = bv0.y;
        Bs[acol + 2][boff] = bv0.z; Bs[acol + 3][boff] = bv0.w;
        Bs[acol + 4][boff] = bv1.x; Bs[acol + 5][boff] = bv1.y;
        Bs[acol + 6][boff] = bv1.z; Bs[acol + 7][boff] = bv1.w;
        __syncthreads();
        if (k0 + 16 < 512) {
            av0 = *(const float4*)(Arow + k0 + 16 + acol);
            av1 = *(const float4*)(Arow + k0 + 16 + acol + 4);
            bv0 = *(const float4*)(Brow + k0 + 16 + acol);
            bv1 = *(const float4*)(Brow + k0 + 16 + acol + 4);
        }
#pragma unroll
        for (int kk = 0; kk < 16; ++kk) {
            const ulonglong2* pA = (const ulonglong2*)&As[kk][ty * 8];
            ulonglong2 qa0 = pA[0], qa1 = pA[1];
            u64 ra[4] = {qa0.x, qa0.y, qa1.x, qa1.y};
            float4 b0v = *(float4*)&Bs[kk][tx * 12];
            float4 b1v = *(float4*)&Bs[kk][tx * 12 + 4];
            u64 rb[8] = {SPLAT2(b0v.x), SPLAT2(b0v.y), SPLAT2(b0v.z), SPLAT2(b0v.w),
                         SPLAT2(b1v.x), SPLAT2(b1v.y), SPLAT2(b1v.z), SPLAT2(b1v.w)};
#pragma unroll
            for (int i = 0; i < 4; ++i)
#pragma unroll
                for (int j = 0; j < 8; ++j) FMA2(acc2[i][j], ra[i], rb[j]);
        }
    }
#pragma unroll
    for (int i2 = 0; i2 < 4; ++i2) {
        int rr = ty * 8 + i2 * 2;
        int ob = b0 + (rr >> 6);
        int os = s0 + (rr & 63);
        float* oe = &g_xw[dir][ob * TT + os][0];
        float* oo = oe + G4;
#pragma unroll
        for (int j = 0; j < 8; ++j) {
            int n = tx * 8 + j;
            float lo, hi; UNPACK2(acc2[i2][j], lo, hi);
            float bb = bias_s[n];
            oe[n0 + n] = lo + bb;
            oo[n0 + n] = hi + bb;
        }
    }
}

// ---------------- persistent recurrence v12: 512 threads / 16 warps per CTA ----------------
// 128 CTAs: [0,64)=fwd, [64,128)=bwd. CTA owns 8 h-cols (32 gate rows).
// Warp w (0..15) owns gate rows 2w..2w+1; lane owns k-slice [16*lane, 16*lane+16).
// 2x the warps of v11 -> hides SHFL/LDS latency. 5-SHFL reduction per warp per b.
__global__ __launch_bounds__(512, 1) void k_recur(const float* Wh_f, const float* Wh_b,
                                                  const int* lengths, float* d_out) {
    extern __shared__ float sm_f[];
    float* h_s     = sm_f;                       // 64 * 648 padded h
    float* gates_s = sm_f + 64 * HPAD;           // 64 * 32
    float* c_s     = gates_s + 64 * 32;          // 512
    float* hn_s    = c_s + 512;                  // 512 persistent current h
    int*   len_s   = (int*)(hn_s + 512);         // 64

    int dir = blockIdx.x >> 6;
    int cid = blockIdx.x & 63;
    int j0 = cid * 8;
    const float* Wh = dir ? Wh_b : Wh_f;
    int tid = threadIdx.x;
    int w = tid >> 5, lane = tid & 31;

    if (tid < 64) len_s[tid] = lengths[tid];
    if (tid < 512) { c_s[tid] = 0.f; hn_s[tid] = 0.f; }

    // weights: rows 2w, 2w+1; k-slice lane*16 .. +16 (8 u64 per row)
    u64 wq[2][8];
#pragma unroll
    for (int r = 0; r < 2; ++r) {
        int lr = w * 2 + r;
        int grow = (lr >> 3) * 512 + j0 + (lr & 7);
        const ulonglong2* wsrc = (const ulonglong2*)(Wh + (size_t)grow * 512 + lane * 16);
#pragma unroll
        for (int q = 0; q < 4; ++q) {
            ulonglong2 v = wsrc[q];
            wq[r][2 * q] = v.x; wq[r][2 * q + 1] = v.y;
        }
    }
    __syncthreads();

    unsigned* flags = &g_flags[dir][0];
    int nact = 64;

    // prefetch xg for t=0: one (b,jj) item per thread
    float xg[4];
    {
        int b = tid >> 3, jj = tid & 7;
        const float* xwrow = &g_xw[dir][b * TT + 0][0];
        int col = j0 + jj;
        xg[0] = xwrow[col];
        xg[1] = xwrow[512 + col];
        xg[2] = xwrow[1024 + col];
        xg[3] = xwrow[1536 + col];
    }

    for (int t = 0; t < TT; ++t) {
        if (nact == 0) break;

        // ---- stage h_prev: coalesced LDG, conflict-free scattered STS ----
        {
            int nact2 = 8;
            while (nact2 < nact) nact2 <<= 1;
            int lg = __ffs(nact2) - 1;
            const float4* hr4 = (const float4*)&g_h2[dir][t & 1][0][0][0];
            float4* hs4 = (float4*)h_s;
            int total = (64 << lg) << 1;
            for (int i = tid; i < total; i += 512) {
                int half = i & 1;
                int b = (i >> 1) & (nact2 - 1);
                int c2 = i >> (1 + lg);
                float4 v = hr4[c2 * 128 + b * 2 + half];
                hs4[b * (HPAD / 4) + (c2 >> 1) * 5 + (c2 & 1) * 2 + half] = v;
            }
        }
        __syncthreads();

        // ---- Wh @ h from smem: per warp per b: 4 LDS.128 + 16 FMA2 + 5 SHFL ----
#pragma unroll 4
        for (int b = 0; b < nact; ++b) {
            const ulonglong2* hp = (const ulonglong2*)(h_s + b * HPAD + lane * 20);
            ulonglong2 v0 = hp[0], v1 = hp[1], v2 = hp[2], v3 = hp[3];
            u64 hv[8] = {v0.x, v0.y, v1.x, v1.y, v2.x, v2.y, v3.x, v3.y};
            u64 a0 = 0ULL, a1 = 0ULL;
#pragma unroll
            for (int q = 0; q < 8; ++q) {
                FMA2(a0, wq[0][q], hv[q]);
                FMA2(a1, wq[1][q], hv[q]);
            }
            float s0 = HADD2(a0), s1 = HADD2(a1);
            float u  = (lane & 1) ? s1 : s0;
            float us = (lane & 1) ? s0 : s1;
            u += __shfl_xor_sync(0xffffffffu, us, 1);
            u += __shfl_xor_sync(0xffffffffu, u, 2);
            u += __shfl_xor_sync(0xffffffffu, u, 4);
            u += __shfl_xor_sync(0xffffffffu, u, 8);
            u += __shfl_xor_sync(0xffffffffu, u, 16);
            if (lane < 2) gates_s[b * 32 + w * 2 + lane] = u;
        }
        __syncthreads();

        // ---- gate math + direct coalesced h publish + hn in register ----
        float hnv = 0.f;
        float* hw = &g_h2[dir][(t + 1) & 1][cid][0][0];
        {
            int b = tid >> 3, jj = tid & 7;
            if (b < nact) {
                float gi = gates_s[b * 32 + jj]      + xg[0];
                float gf = gates_s[b * 32 + 8 + jj]  + xg[1];
                float gg = gates_s[b * 32 + 16 + jj] + xg[2];
                float go = gates_s[b * 32 + 24 + jj] + xg[3];
                gi = 1.f / (1.f + __expf(-gi));
                gf = 1.f / (1.f + __expf(-gf));
                gg = tanhf(gg);
                go = 1.f / (1.f + __expf(-go));
                float c = gf * c_s[tid] + gi * gg;
                c_s[tid] = c;
                float hn = go * tanhf(c);
                hn_s[tid] = hn;
                hw[tid] = hn;                 // coalesced STG.32 publish
                hnv = hn;
            }
        }
        __syncthreads();
        if (tid == 0) ST_REL(&flags[cid * 8], (unsigned)(t + 1));

        // ---- hidden in barrier wait: d_out store (from reg) + next xg prefetch ----
        {
            int b = tid >> 3, jj = tid & 7;
            if (b < nact) {
                int tout = dir ? (len_s[b] - 1 - t) : t;
                d_out[((size_t)(b * TT + tout)) * 1024 + (size_t)dir * 512 + j0 + jj] = hnv;
            }
        }
        int nn = nact;
        while (nn > 0 && len_s[nn - 1] <= t + 1) --nn;
        {
            int b = tid >> 3, jj = tid & 7;
            if (b < nn) {
                const float* xwrow = &g_xw[dir][b * TT + (t + 1)][0];
                int col = j0 + jj;
                xg[0] = xwrow[col];
                xg[1] = xwrow[512 + col];
                xg[2] = xwrow[1024 + col];
                xg[3] = xwrow[1536 + col];
            }
        }

        // ---- parallel acquire-poll: thread i waits on CTA i's flag ----
        if (tid < 64) {
            while (LD_ACQ(&flags[tid * 8]) < (unsigned)(t + 1)) { }
        }
        __syncthreads();
        nact = nn;
    }

    // ---- final hidden h / c ----
    {
        int b = tid >> 3, jj = tid & 7;
        int col = j0 + jj;
        d_out[OUT1_O + (size_t)b * 1024 + (size_t)dir * 512 + col] = hn_s[tid];
        d_out[OUT2_O + (size_t)b * 1024 + (size_t)dir * 512 + col] = c_s[tid];
    }
}

// ---------------- launch ----------------
extern "C" void kernel_launch(void* const* d_in, const int* in_sizes, int n_in,
                              void* d_out, int out_size) {
    const void*  act_mask  = d_in[0];
    const int*   act_ids   = (const int*)d_in[1];
    const int*   obs_ids   = (const int*)d_in[2];
    const float* res_feats = (const float*)d_in[3];
    const int*   lengths   = (const int*)d_in[4];
    const float* act_emb   = (const float*)d_in[5];
    const float* obs_emb   = (const float*)d_in[6];
    const float* W_res     = (const float*)d_in[7];
    const float* b_res     = (const float*)d_in[8];
    const float* Wi_f      = (const float*)d_in[9];
    const float* Wh_f      = (const float*)d_in[10];
    const float* bi_f      = (const float*)d_in[11];
    const float* bh_f      = (const float*)d_in[12];
    const float* Wi_b      = (const float*)d_in[13];
    const float* Wh_b      = (const float*)d_in[14];
    const float* bi_b      = (const float*)d_in[15];
    const float* bh_b      = (const float*)d_in[16];

    float* out = (float*)d_out;
    float* emb_out = out + OUT3_O;

    cudaFuncSetAttribute(k_recur, cudaFuncAttributeMaxDynamicSharedMemorySize, SMEM_RECUR);

    k_init<<<2048, 256>>>(out, (const unsigned int*)act_mask);
    k_res<<<512, 256>>>(res_feats, W_res, b_res, act_mask,
                        act_ids, obs_ids, act_emb, obs_emb, emb_out);
    {
        dim3 g(G4 / 128, (BB * TT) / 128, 2);
        k_xw<<<g, 256>>>(emb_out, Wi_f, bi_f, bh_f, Wi_b, bi_b, bh_b, lengths);
    }
    k_recur<<<128, 512, SMEM_RECUR>>>(Wh_f, Wh_b, lengths, out);
}